// round 5
// baseline (speedup 1.0000x reference)
#include <cuda_runtime.h>
#include <cuda_fp16.h>
#include <math.h>
#include <stdint.h>

// Problem constants
#define BQ   16
#define NP   2048
#define DF   256
#define NH   8
#define DHD  64
#define KN   8
#define ID   512
#define QKV3 1536
#define RAD2 0.09f
#define LNEPS 1e-5f

// Scratch (static device globals; runtime allocation is forbidden)
__device__ int    g_idx[BQ * NP * KN];
__device__ __half g_qkv_h[BQ * NP * QKV3];
__device__ __half g_ao_h[BQ * NP * ID];
__device__ __half g_wqkv_h[DF * QKV3];
__device__ __half g_wout_h[ID * DF];

// ---------------------------------------------------------------------------
// PTX helpers
// ---------------------------------------------------------------------------
__device__ __forceinline__ void mma_f16(float* c, const uint32_t* a, const uint32_t* b) {
    asm volatile(
        "mma.sync.aligned.m16n8k16.row.col.f32.f16.f16.f32 "
        "{%0,%1,%2,%3}, {%4,%5,%6,%7}, {%8,%9}, {%0,%1,%2,%3};"
        : "+f"(c[0]), "+f"(c[1]), "+f"(c[2]), "+f"(c[3])
        : "r"(a[0]), "r"(a[1]), "r"(a[2]), "r"(a[3]), "r"(b[0]), "r"(b[1]));
}

__device__ __forceinline__ void ldsm_x4(uint32_t& r0, uint32_t& r1, uint32_t& r2,
                                        uint32_t& r3, uint32_t addr) {
    asm volatile("ldmatrix.sync.aligned.m8n8.x4.shared.b16 {%0,%1,%2,%3}, [%4];"
                 : "=r"(r0), "=r"(r1), "=r"(r2), "=r"(r3) : "r"(addr));
}
__device__ __forceinline__ void ldsm_x4t(uint32_t& r0, uint32_t& r1, uint32_t& r2,
                                         uint32_t& r3, uint32_t addr) {
    asm volatile("ldmatrix.sync.aligned.m8n8.x4.trans.shared.b16 {%0,%1,%2,%3}, [%4];"
                 : "=r"(r0), "=r"(r1), "=r"(r2), "=r"(r3) : "r"(addr));
}

__device__ __forceinline__ void cp16(uint32_t smem_dst, const void* gsrc) {
    asm volatile("cp.async.cg.shared.global [%0], [%1], 16;" :: "r"(smem_dst), "l"(gsrc));
}
__device__ __forceinline__ void cp_commit() { asm volatile("cp.async.commit_group;"); }
template <int N>
__device__ __forceinline__ void cp_wait() { asm volatile("cp.async.wait_group %0;" :: "n"(N)); }

// ---------------------------------------------------------------------------
// Kernel 1: ball_query. Rank-based parallel neighbor collection.
// ---------------------------------------------------------------------------
__global__ void __launch_bounds__(256) ball_kernel(const float* __restrict__ xyzs) {
    __shared__ float sx[NP], sy[NP], sz[NP], s2[NP];
    __shared__ int sres[8][KN];
    const int b = blockIdx.y;
    const float* xb = xyzs + (size_t)b * NP * 3;
    for (int i = threadIdx.x; i < NP; i += 256) {
        float x = xb[3 * i], y = xb[3 * i + 1], z = xb[3 * i + 2];
        sx[i] = x; sy[i] = y; sz[i] = z;
        s2[i] = x * x + y * y + z * z;
    }
    __syncthreads();
    const int warp = threadIdx.x >> 5, lane = threadIdx.x & 31;
    const unsigned lt_mask = (1u << lane) - 1u;
    for (int qi = 0; qi < 8; qi++) {
        const int n = blockIdx.x * 64 + warp * 8 + qi;
        const float qx = sx[n], qy = sy[n], qz = sz[n], q2 = s2[n];
        int found = 0;
        for (int t = 0; t < NP && found < KN; t += 32) {
            const int m = t + lane;
            float d2 = q2 + s2[m] - 2.0f * (qx * sx[m] + qy * sy[m] + qz * sz[m]);
            const bool hit = d2 < RAD2;
            unsigned mask = __ballot_sync(0xffffffffu, hit);
            if (hit) {
                int slot = found + __popc(mask & lt_mask);
                if (slot < KN) sres[warp][slot] = m;
            }
            found += __popc(mask);
        }
        __syncwarp();
        if (lane < KN) {
            int v = sres[warp][lane < found ? lane : 0];
            g_idx[((size_t)b * NP + n) * KN + lane] = v;
        }
        __syncwarp();
    }
}

// ---------------------------------------------------------------------------
// Weight conversion fp32 -> fp16
// ---------------------------------------------------------------------------
__global__ void __launch_bounds__(256) conv_kernel(const float* __restrict__ src,
                                                   __half* __restrict__ dst) {
    const int i = (blockIdx.x * 256 + threadIdx.x) * 4;
    float4 v = *(const float4*)(src + i);
    __half2* d = (__half2*)(dst + i);
    d[0] = __floats2half2_rn(v.x, v.y);
    d[1] = __floats2half2_rn(v.z, v.w);
}

// ---------------------------------------------------------------------------
// Kernel 2: fused LayerNorm + QKV GEMM.
//   C[32768 x 1536] = LN(feature)[32768 x 256] @ w_qkv[256 x 1536], fp16 out.
// Block: 128x128 tile, 256 threads, 8 warps (4x2), m16n8k16 mma.
// A panel (128 x 256, fp16 after in-kernel LN) fully resident in smem.
// All 8 B k-tiles (32 x 128 each) prefetched via cp.async, 1 group/tile,
// overlapped with the LN compute. Mainloop has zero global loads.
//   As stride 264 halves (132 words; 132 mod 32 = 4 -> ldmatrix conflict-free)
//   Bs stride 136 halves (68 words; 68 mod 32 = 4 -> conflict-free)
// ---------------------------------------------------------------------------
#define ASH2 264
#define BSH  136
#define AS_HALVES (128 * ASH2)
#define BTILE_HALVES (32 * BSH)
#define QKV_SMEM_BYTES ((AS_HALVES + 8 * BTILE_HALVES) * 2)

__global__ void __launch_bounds__(256) qkv_fused_kernel(
    const float* __restrict__ feature, const float* __restrict__ gam,
    const float* __restrict__ bet, const __half* __restrict__ Bm,
    __half* __restrict__ C) {
    extern __shared__ __half sh[];
    __half* As = sh;
    __half* Bs = sh + AS_HALVES;

    const int tid = threadIdx.x;
    const int warp = tid >> 5, lane = tid & 31;
    const int warp_m = warp >> 1, warp_n = warp & 1;
    const int brow = blockIdx.y * 128;
    const int bcol = blockIdx.x * 128;

    // ---- prefetch all 8 B k-tiles (one commit group per tile) ----
    const int b_r0 = tid >> 4;        // 0..15
    const int b_c = (tid & 15) * 8;   // halves 0..120
#pragma unroll
    for (int kt = 0; kt < 8; kt++) {
        const uint32_t bs_base = (uint32_t)__cvta_generic_to_shared(Bs + kt * BTILE_HALVES);
#pragma unroll
        for (int i = 0; i < 2; i++) {
            const int row = b_r0 + 16 * i;
            cp16(bs_base + (row * BSH + b_c) * 2,
                 Bm + (size_t)(kt * 32 + row) * QKV3 + bcol + b_c);
        }
        cp_commit();
    }

    // ---- LayerNorm of this block's 128 A rows -> As (fp16) ----
    {
        const float* gp = gam + lane * 8;
        const float* bp = bet + lane * 8;
        float gv[8], bv[8];
        float4 g0 = *(const float4*)gp, g1 = *(const float4*)(gp + 4);
        float4 bb0 = *(const float4*)bp, bb1 = *(const float4*)(bp + 4);
        gv[0] = g0.x; gv[1] = g0.y; gv[2] = g0.z; gv[3] = g0.w;
        gv[4] = g1.x; gv[5] = g1.y; gv[6] = g1.z; gv[7] = g1.w;
        bv[0] = bb0.x; bv[1] = bb0.y; bv[2] = bb0.z; bv[3] = bb0.w;
        bv[4] = bb1.x; bv[5] = bb1.y; bv[6] = bb1.z; bv[7] = bb1.w;
#pragma unroll 1
        for (int r8 = 0; r8 < 16; r8++) {
            const int row = warp * 16 + r8;
            const float* f = feature + (size_t)(brow + row) * DF + lane * 8;
            float v[8];
            float4 v0 = *(const float4*)f;
            float4 v1 = *(const float4*)(f + 4);
            v[0] = v0.x; v[1] = v0.y; v[2] = v0.z; v[3] = v0.w;
            v[4] = v1.x; v[5] = v1.y; v[6] = v1.z; v[7] = v1.w;
            float s = 0.f;
#pragma unroll
            for (int i = 0; i < 8; i++) s += v[i];
#pragma unroll
            for (int o = 16; o; o >>= 1) s += __shfl_xor_sync(0xffffffffu, s, o);
            const float mu = s * (1.0f / DF);
            float sq = 0.f;
#pragma unroll
            for (int i = 0; i < 8; i++) { float d = v[i] - mu; sq += d * d; }
#pragma unroll
            for (int o = 16; o; o >>= 1) sq += __shfl_xor_sync(0xffffffffu, sq, o);
            const float rs = rsqrtf(sq * (1.0f / DF) + LNEPS);
            __half2* op = (__half2*)(As + row * ASH2 + lane * 8);
#pragma unroll
            for (int i = 0; i < 4; i++) {
                float a = (v[2 * i] - mu) * rs * gv[2 * i] + bv[2 * i];
                float c = (v[2 * i + 1] - mu) * rs * gv[2 * i + 1] + bv[2 * i + 1];
                op[i] = __floats2half2_rn(a, c);
            }
        }
    }
    __syncthreads();   // A panel ready for all warps

    float acc[2][8][4];
#pragma unroll
    for (int mt = 0; mt < 2; mt++)
#pragma unroll
        for (int nt = 0; nt < 8; nt++)
#pragma unroll
            for (int r = 0; r < 4; r++) acc[mt][nt][r] = 0.f;

    const int lg = lane >> 2;
    const int lt = lane & 3;
    const int a_lrow = (lane & 15);
    const int a_lcol = ((lane >> 4) << 3);
    const int b_lk = (lane & 7) + ((lane >> 3) & 1) * 8;
    const int b_ln = ((lane >> 4) << 3);

    const uint32_t as_u = (uint32_t)__cvta_generic_to_shared(As);

#pragma unroll
    for (int kt = 0; kt < 8; kt++) {
        // wait until B tile kt has landed (groups committed in tile order)
        switch (kt) {
            case 0: cp_wait<7>(); break;
            case 1: cp_wait<6>(); break;
            case 2: cp_wait<5>(); break;
            case 3: cp_wait<4>(); break;
            case 4: cp_wait<3>(); break;
            case 5: cp_wait<2>(); break;
            case 6: cp_wait<1>(); break;
            default: cp_wait<0>(); break;
        }
        __syncthreads();
        const uint32_t bs_u = (uint32_t)__cvta_generic_to_shared(Bs + kt * BTILE_HALVES);
#pragma unroll
        for (int ks = 0; ks < 2; ks++) {
            uint32_t af[2][4], bf[8][2];
#pragma unroll
            for (int mt = 0; mt < 2; mt++) {
                const int row = warp_m * 32 + mt * 16 + a_lrow;
                const int col = kt * 32 + ks * 16 + a_lcol;
                ldsm_x4(af[mt][0], af[mt][1], af[mt][2], af[mt][3],
                        as_u + (row * ASH2 + col) * 2);
            }
#pragma unroll
            for (int np = 0; np < 4; np++) {
                const int k = ks * 16 + b_lk;
                const int n = warp_n * 64 + np * 16 + b_ln;
                ldsm_x4t(bf[2 * np][0], bf[2 * np][1], bf[2 * np + 1][0], bf[2 * np + 1][1],
                         bs_u + (k * BSH + n) * 2);
            }
#pragma unroll
            for (int mt = 0; mt < 2; mt++)
#pragma unroll
                for (int nt = 0; nt < 8; nt++)
                    mma_f16(acc[mt][nt], af[mt], bf[nt]);
        }
    }

    // epilogue: fp16 store
#pragma unroll
    for (int mt = 0; mt < 2; mt++)
#pragma unroll
        for (int nt = 0; nt < 8; nt++) {
            const int r = brow + warp_m * 32 + mt * 16 + lg;
            const int c = bcol + warp_n * 64 + nt * 8 + 2 * lt;
#pragma unroll
            for (int h = 0; h < 2; h++) {
                const int rr = r + h * 8;
                *(__half2*)(C + (size_t)rr * QKV3 + c) =
                    __floats2half2_rn(acc[mt][nt][h * 2 + 0], acc[mt][nt][h * 2 + 1]);
            }
        }
}

// ---------------------------------------------------------------------------
// Kernel 4: out GEMM (fp16 A/B, fp32 accum) with GELU + residual epilogue.
// Same structure as round 4 hgemm (EPI=1).
// ---------------------------------------------------------------------------
#define ASH 40

__global__ void __launch_bounds__(256) out_gemm_kernel(
    const __half* __restrict__ A, const __half* __restrict__ Bm, float* __restrict__ C,
    const float* __restrict__ bias, const float* __restrict__ resid) {
    __shared__ __half As[2][128 * ASH];
    __shared__ __half Bs[2][32 * BSH];
    const int N = DF, Kd = ID;

    const int tid = threadIdx.x;
    const int warp = tid >> 5, lane = tid & 31;
    const int warp_m = warp >> 1, warp_n = warp & 1;
    const int brow = blockIdx.y * 128;
    const int bcol = blockIdx.x * 128;
    const int KT = Kd / 32;

    const int a_r0 = tid >> 2;
    const int a_c = (tid & 3) * 8;
    const int b_r0 = tid >> 4;
    const int b_c = (tid & 15) * 8;

    auto load_tile = [&](int kt, int buf) {
        const uint32_t as_base = (uint32_t)__cvta_generic_to_shared(&As[buf][0]);
        const uint32_t bs_base = (uint32_t)__cvta_generic_to_shared(&Bs[buf][0]);
#pragma unroll
        for (int i = 0; i < 2; i++) {
            const int row = a_r0 + 64 * i;
            cp16(as_base + (row * ASH + a_c) * 2,
                 A + (size_t)(brow + row) * Kd + kt * 32 + a_c);
        }
#pragma unroll
        for (int i = 0; i < 2; i++) {
            const int row = b_r0 + 16 * i;
            cp16(bs_base + (row * BSH + b_c) * 2,
                 Bm + (size_t)(kt * 32 + row) * N + bcol + b_c);
        }
        cp_commit();
    };

    float acc[2][8][4];
#pragma unroll
    for (int mt = 0; mt < 2; mt++)
#pragma unroll
        for (int nt = 0; nt < 8; nt++)
#pragma unroll
            for (int r = 0; r < 4; r++) acc[mt][nt][r] = 0.f;

    load_tile(0, 0);

    const int lg = lane >> 2;
    const int lt = lane & 3;
    const int a_lrow = (lane & 15);
    const int a_lcol = ((lane >> 4) << 3);
    const int b_lk = (lane & 7) + ((lane >> 3) & 1) * 8;
    const int b_ln = ((lane >> 4) << 3);

    for (int kt = 0; kt < KT; kt++) {
        const int buf = kt & 1;
        if (kt + 1 < KT) {
            load_tile(kt + 1, buf ^ 1);
            cp_wait<1>();
        } else {
            cp_wait<0>();
        }
        __syncthreads();

        const uint32_t as_u = (uint32_t)__cvta_generic_to_shared(&As[buf][0]);
        const uint32_t bs_u = (uint32_t)__cvta_generic_to_shared(&Bs[buf][0]);
#pragma unroll
        for (int ks = 0; ks < 2; ks++) {
            uint32_t af[2][4], bf[8][2];
#pragma unroll
            for (int mt = 0; mt < 2; mt++) {
                const int row = warp_m * 32 + mt * 16 + a_lrow;
                const int col = ks * 16 + a_lcol;
                ldsm_x4(af[mt][0], af[mt][1], af[mt][2], af[mt][3],
                        as_u + (row * ASH + col) * 2);
            }
#pragma unroll
            for (int np = 0; np < 4; np++) {
                const int k = ks * 16 + b_lk;
                const int n = warp_n * 64 + np * 16 + b_ln;
                ldsm_x4t(bf[2 * np][0], bf[2 * np][1], bf[2 * np + 1][0], bf[2 * np + 1][1],
                         bs_u + (k * BSH + n) * 2);
            }
#pragma unroll
            for (int mt = 0; mt < 2; mt++)
#pragma unroll
                for (int nt = 0; nt < 8; nt++)
                    mma_f16(acc[mt][nt], af[mt], bf[nt]);
        }
        __syncthreads();
    }

#pragma unroll
    for (int mt = 0; mt < 2; mt++)
#pragma unroll
        for (int nt = 0; nt < 8; nt++) {
            const int r = brow + warp_m * 32 + mt * 16 + lg;
            const int c = bcol + warp_n * 64 + nt * 8 + 2 * lt;
#pragma unroll
            for (int h = 0; h < 2; h++) {
                const int rr = r + h * 8;
                const float* rp = resid + (size_t)rr * N + c;
                float a0 = acc[mt][nt][h * 2 + 0] + bias[c];
                float a1 = acc[mt][nt][h * 2 + 1] + bias[c + 1];
                float g0 = 0.5f * a0 * (1.0f + erff(a0 * 0.70710678118654752f));
                float g1 = 0.5f * a1 * (1.0f + erff(a1 * 0.70710678118654752f));
                float2 o = {g0 + rp[0], g1 + rp[1]};
                *(float2*)(C + (size_t)rr * N + c) = o;
            }
        }
}

// ---------------------------------------------------------------------------
// Kernel 3: attention over K=8 neighbors + spatial op, fp16 q/k/v.
// ---------------------------------------------------------------------------
__global__ void __launch_bounds__(256) attn_kernel(const float* __restrict__ xyzs,
                                                   const float* __restrict__ w_sp) {
    const int p = blockIdx.x;
    const int b = p >> 11;
    const int warp = threadIdx.x >> 5;
    const int lane = threadIdx.x & 31;

    __shared__ int sidx[KN];
    __shared__ float sdisp[KN][3];
    if (threadIdx.x < KN) sidx[threadIdx.x] = g_idx[(size_t)p * KN + threadIdx.x];
    __syncthreads();
    if (threadIdx.x < KN * 3) {
        int j = threadIdx.x / 3, c = threadIdx.x % 3;
        sdisp[j][c] = xyzs[((size_t)b * NP + sidx[j]) * 3 + c] - xyzs[(size_t)p * 3 + c];
    }
    __syncthreads();

    const size_t qoff = (size_t)p * QKV3 + warp * DHD + 2 * lane;
    const __half2 q2 = *(const __half2*)(g_qkv_h + qoff);
    const float qx = __low2float(q2), qy = __high2float(q2);

    float logits[KN];
#pragma unroll
    for (int j = 0; j < KN; j++) {
        const size_t koff = ((size_t)b * NP + sidx[j]) * QKV3 + ID + warp * DHD + 2 * lane;
        const __half2 k2 = *(const __half2*)(g_qkv_h + koff);
        float d = qx * __low2float(k2) + qy * __high2float(k2);
#pragma unroll
        for (int o = 16; o; o >>= 1) d += __shfl_xor_sync(0xffffffffu, d, o);
        logits[j] = d * 0.125f;
    }

    float mx = logits[0];
#pragma unroll
    for (int j = 1; j < KN; j++) mx = fmaxf(mx, logits[j]);
    float a[KN];
    float se = 0.f;
#pragma unroll
    for (int j = 0; j < KN; j++) { a[j] = expf(logits[j] - mx); se += a[j]; }
    const float inv = 1.0f / se;
#pragma unroll
    for (int j = 0; j < KN; j++) a[j] *= inv;

    float oa = 0.f, ob = 0.f;
#pragma unroll
    for (int j = 0; j < KN; j++) {
        const size_t voff = ((size_t)b * NP + sidx[j]) * QKV3 + 2 * ID + warp * DHD + 2 * lane;
        const __half2 v2 = *(const __half2*)(g_qkv_h + voff);
        oa = fmaf(a[j], __low2float(v2), oa);
        ob = fmaf(a[j], __high2float(v2), ob);
    }

    float dm[3];
#pragma unroll
    for (int c = 0; c < 3; c++) {
        float m = a[0] * sdisp[0][c];
#pragma unroll
        for (int j = 1; j < KN; j++) m = fmaxf(m, a[j] * sdisp[j][c]);
        dm[c] = m;
    }
    const int d0 = 2 * lane, d1 = 2 * lane + 1;
    const float da = dm[0] * w_sp[d0] + dm[1] * w_sp[64 + d0] + dm[2] * w_sp[128 + d0];
    const float db = dm[0] * w_sp[d1] + dm[1] * w_sp[64 + d1] + dm[2] * w_sp[128 + d1];

    __half2* op = (__half2*)(g_ao_h + (size_t)p * ID + warp * DHD + 2 * lane);
    *op = __floats2half2_rn(oa + da, ob + db);
}

// ---------------------------------------------------------------------------
extern "C" void kernel_launch(void* const* d_in, const int* in_sizes, int n_in,
                              void* d_out, int out_size) {
    (void)in_sizes; (void)n_in; (void)out_size;
    const float* xyzs    = (const float*)d_in[0];
    const float* feature = (const float*)d_in[1];
    const float* ln_g    = (const float*)d_in[2];
    const float* ln_b    = (const float*)d_in[3];
    const float* w_qkv   = (const float*)d_in[4];
    const float* w_sp    = (const float*)d_in[5];
    const float* w_out   = (const float*)d_in[6];
    const float* b_out   = (const float*)d_in[7];
    float* out = (float*)d_out;

    void *p_qkv, *p_ao, *p_wqkv, *p_wout;
    cudaGetSymbolAddress(&p_qkv, g_qkv_h);
    cudaGetSymbolAddress(&p_ao, g_ao_h);
    cudaGetSymbolAddress(&p_wqkv, g_wqkv_h);
    cudaGetSymbolAddress(&p_wout, g_wout_h);
    __half* qkv = (__half*)p_qkv;
    __half* ao = (__half*)p_ao;
    __half* wqkv = (__half*)p_wqkv;
    __half* wout = (__half*)p_wout;

    cudaFuncSetAttribute(qkv_fused_kernel, cudaFuncAttributeMaxDynamicSharedMemorySize,
                         QKV_SMEM_BYTES);

    // weight conversions
    conv_kernel<<<(DF * QKV3) / 1024, 256>>>(w_qkv, wqkv);
    conv_kernel<<<(ID * DF) / 1024, 256>>>(w_out, wout);
    // 1) ball query
    ball_kernel<<<dim3(NP / 64, BQ), 256>>>(xyzs);
    // 2) fused LN + qkv GEMM -> fp16
    qkv_fused_kernel<<<dim3(QKV3 / 128, (BQ * NP) / 128), 256, QKV_SMEM_BYTES>>>(
        feature, ln_g, ln_b, wqkv, qkv);
    // 3) attention + spatial op -> g_ao (fp16)
    attn_kernel<<<BQ * NP, 256>>>(xyzs, w_sp);
    // 4) out = gelu(ao @ w_out + b_out) + feature -> fp32
    out_gemm_kernel<<<dim3(DF / 128, (BQ * NP) / 128), 256>>>(
        ao, wout, out, b_out, feature);
}

// round 6
// speedup vs baseline: 1.4545x; 1.4545x over previous
#include <cuda_runtime.h>
#include <cuda_fp16.h>
#include <math.h>
#include <stdint.h>

// Problem constants
#define BQ   16
#define NP   2048
#define DF   256
#define NH   8
#define DHD  64
#define KN   8
#define ID   512
#define QKV3 1536
#define RAD2 0.09f
#define LNEPS 1e-5f

// Scratch (static device globals; runtime allocation is forbidden)
__device__ int    g_idx[BQ * NP * KN];
__device__ __half g_normed_h[BQ * NP * DF];
__device__ __half g_qkv_h[BQ * NP * QKV3];
__device__ __half g_ao_h[BQ * NP * ID];
__device__ __half g_wqkv_h[DF * QKV3];
__device__ __half g_wout_h[ID * DF];

// ---------------------------------------------------------------------------
// PTX helpers
// ---------------------------------------------------------------------------
__device__ __forceinline__ void mma_f16(float* c, const uint32_t* a, const uint32_t* b) {
    asm volatile(
        "mma.sync.aligned.m16n8k16.row.col.f32.f16.f16.f32 "
        "{%0,%1,%2,%3}, {%4,%5,%6,%7}, {%8,%9}, {%0,%1,%2,%3};"
        : "+f"(c[0]), "+f"(c[1]), "+f"(c[2]), "+f"(c[3])
        : "r"(a[0]), "r"(a[1]), "r"(a[2]), "r"(a[3]), "r"(b[0]), "r"(b[1]));
}

__device__ __forceinline__ void ldsm_x4(uint32_t& r0, uint32_t& r1, uint32_t& r2,
                                        uint32_t& r3, uint32_t addr) {
    asm volatile("ldmatrix.sync.aligned.m8n8.x4.shared.b16 {%0,%1,%2,%3}, [%4];"
                 : "=r"(r0), "=r"(r1), "=r"(r2), "=r"(r3) : "r"(addr));
}
__device__ __forceinline__ void ldsm_x4t(uint32_t& r0, uint32_t& r1, uint32_t& r2,
                                         uint32_t& r3, uint32_t addr) {
    asm volatile("ldmatrix.sync.aligned.m8n8.x4.trans.shared.b16 {%0,%1,%2,%3}, [%4];"
                 : "=r"(r0), "=r"(r1), "=r"(r2), "=r"(r3) : "r"(addr));
}

__device__ __forceinline__ void cp16(uint32_t smem_dst, const void* gsrc) {
    asm volatile("cp.async.cg.shared.global [%0], [%1], 16;" :: "r"(smem_dst), "l"(gsrc));
}
__device__ __forceinline__ void cp_commit() { asm volatile("cp.async.commit_group;"); }
template <int N>
__device__ __forceinline__ void cp_wait() { asm volatile("cp.async.wait_group %0;" :: "n"(N)); }

// ---------------------------------------------------------------------------
// Kernel 1: ball_query. Rank-based parallel neighbor collection.
// ---------------------------------------------------------------------------
__global__ void __launch_bounds__(256) ball_kernel(const float* __restrict__ xyzs) {
    __shared__ float sx[NP], sy[NP], sz[NP], s2[NP];
    __shared__ int sres[8][KN];
    const int b = blockIdx.y;
    const float* xb = xyzs + (size_t)b * NP * 3;
    for (int i = threadIdx.x; i < NP; i += 256) {
        float x = xb[3 * i], y = xb[3 * i + 1], z = xb[3 * i + 2];
        sx[i] = x; sy[i] = y; sz[i] = z;
        s2[i] = x * x + y * y + z * z;
    }
    __syncthreads();
    const int warp = threadIdx.x >> 5, lane = threadIdx.x & 31;
    const unsigned lt_mask = (1u << lane) - 1u;
    for (int qi = 0; qi < 8; qi++) {
        const int n = blockIdx.x * 64 + warp * 8 + qi;
        const float qx = sx[n], qy = sy[n], qz = sz[n], q2 = s2[n];
        int found = 0;
        for (int t = 0; t < NP && found < KN; t += 32) {
            const int m = t + lane;
            float d2 = q2 + s2[m] - 2.0f * (qx * sx[m] + qy * sy[m] + qz * sz[m]);
            const bool hit = d2 < RAD2;
            unsigned mask = __ballot_sync(0xffffffffu, hit);
            if (hit) {
                int slot = found + __popc(mask & lt_mask);
                if (slot < KN) sres[warp][slot] = m;
            }
            found += __popc(mask);
        }
        __syncwarp();
        if (lane < KN) {
            int v = sres[warp][lane < found ? lane : 0];
            g_idx[((size_t)b * NP + n) * KN + lane] = v;
        }
        __syncwarp();
    }
}

// ---------------------------------------------------------------------------
// Kernel 2: LayerNorm -> fp16 output
// ---------------------------------------------------------------------------
__global__ void __launch_bounds__(256) ln_kernel(const float* __restrict__ feature,
                                                 const float* __restrict__ gam,
                                                 const float* __restrict__ bet) {
    const int row = blockIdx.x * 8 + (threadIdx.x >> 5);
    const int lane = threadIdx.x & 31;
    const float* f = feature + (size_t)row * DF + lane * 8;
    float v[8];
    float4 v0 = *(const float4*)f;
    float4 v1 = *(const float4*)(f + 4);
    v[0] = v0.x; v[1] = v0.y; v[2] = v0.z; v[3] = v0.w;
    v[4] = v1.x; v[5] = v1.y; v[6] = v1.z; v[7] = v1.w;
    float s = 0.f;
#pragma unroll
    for (int i = 0; i < 8; i++) s += v[i];
#pragma unroll
    for (int o = 16; o; o >>= 1) s += __shfl_xor_sync(0xffffffffu, s, o);
    const float mu = s * (1.0f / DF);
    float sq = 0.f;
#pragma unroll
    for (int i = 0; i < 8; i++) { float d = v[i] - mu; sq += d * d; }
#pragma unroll
    for (int o = 16; o; o >>= 1) sq += __shfl_xor_sync(0xffffffffu, sq, o);
    const float rs = rsqrtf(sq * (1.0f / DF) + LNEPS);
    const float* gp = gam + lane * 8;
    const float* bp = bet + lane * 8;
    __half2 o[4];
#pragma unroll
    for (int i = 0; i < 4; i++) {
        float a = (v[2 * i] - mu) * rs * gp[2 * i] + bp[2 * i];
        float bvl = (v[2 * i + 1] - mu) * rs * gp[2 * i + 1] + bp[2 * i + 1];
        o[i] = __floats2half2_rn(a, bvl);
    }
    __half2* op = (__half2*)(g_normed_h + (size_t)row * DF + lane * 8);
#pragma unroll
    for (int i = 0; i < 4; i++) op[i] = o[i];
}

// ---------------------------------------------------------------------------
// Weight conversion fp32 -> fp16
// ---------------------------------------------------------------------------
__global__ void __launch_bounds__(256) conv_kernel(const float* __restrict__ src,
                                                   __half* __restrict__ dst) {
    const int i = (blockIdx.x * 256 + threadIdx.x) * 4;
    float4 v = *(const float4*)(src + i);
    __half2* d = (__half2*)(dst + i);
    d[0] = __floats2half2_rn(v.x, v.y);
    d[1] = __floats2half2_rn(v.z, v.w);
}

// ---------------------------------------------------------------------------
// Kernel 3/5: fp16 tensor-core GEMM, fp32 accumulate.
// 128x128 block tile, ktile 32, 8 warps (4x2), each warp 32x64 via m16n8k16.
// cp.async double-buffered.  As: [128][40] halves.  Bs: [32][136] halves.
// EPI=0: fp16 store. EPI=1: +bias, exact GELU, +fp32 residual, fp32 store.
// ---------------------------------------------------------------------------
#define ASH 40
#define BSH 136

template <int EPI>
__global__ void __launch_bounds__(256) hgemm_kernel(
    const __half* __restrict__ A, const __half* __restrict__ Bm, void* __restrict__ Cv,
    int N, int Kd, const float* __restrict__ bias, const float* __restrict__ resid) {
    __shared__ __half As[2][128 * ASH];
    __shared__ __half Bs[2][32 * BSH];

    const int tid = threadIdx.x;
    const int warp = tid >> 5, lane = tid & 31;
    const int warp_m = warp >> 1, warp_n = warp & 1;
    const int brow = blockIdx.y * 128;
    const int bcol = blockIdx.x * 128;
    const int KT = Kd / 32;

    const int a_r0 = tid >> 2;        // 0..63
    const int a_c = (tid & 3) * 8;    // halves 0..24
    const int b_r0 = tid >> 4;        // 0..15
    const int b_c = (tid & 15) * 8;   // halves 0..120

    auto load_tile = [&](int kt, int buf) {
        const uint32_t as_base = (uint32_t)__cvta_generic_to_shared(&As[buf][0]);
        const uint32_t bs_base = (uint32_t)__cvta_generic_to_shared(&Bs[buf][0]);
#pragma unroll
        for (int i = 0; i < 2; i++) {
            const int row = a_r0 + 64 * i;
            cp16(as_base + (row * ASH + a_c) * 2,
                 A + (size_t)(brow + row) * Kd + kt * 32 + a_c);
        }
#pragma unroll
        for (int i = 0; i < 2; i++) {
            const int row = b_r0 + 16 * i;
            cp16(bs_base + (row * BSH + b_c) * 2,
                 Bm + (size_t)(kt * 32 + row) * N + bcol + b_c);
        }
        cp_commit();
    };

    float acc[2][8][4];
#pragma unroll
    for (int mt = 0; mt < 2; mt++)
#pragma unroll
        for (int nt = 0; nt < 8; nt++)
#pragma unroll
            for (int r = 0; r < 4; r++) acc[mt][nt][r] = 0.f;

    load_tile(0, 0);

    const int lg = lane >> 2;   // 0..7
    const int lt = lane & 3;    // 0..3

    const int a_lrow = (lane & 15);
    const int a_lcol = ((lane >> 4) << 3);
    const int b_lk = (lane & 7) + ((lane >> 3) & 1) * 8;
    const int b_ln = ((lane >> 4) << 3);

    for (int kt = 0; kt < KT; kt++) {
        const int buf = kt & 1;
        if (kt + 1 < KT) {
            load_tile(kt + 1, buf ^ 1);
            cp_wait<1>();
        } else {
            cp_wait<0>();
        }
        __syncthreads();

        const uint32_t as_u = (uint32_t)__cvta_generic_to_shared(&As[buf][0]);
        const uint32_t bs_u = (uint32_t)__cvta_generic_to_shared(&Bs[buf][0]);

#pragma unroll
        for (int ks = 0; ks < 2; ks++) {
            uint32_t af[2][4], bf[8][2];
#pragma unroll
            for (int mt = 0; mt < 2; mt++) {
                const int row = warp_m * 32 + mt * 16 + a_lrow;
                const int col = ks * 16 + a_lcol;
                ldsm_x4(af[mt][0], af[mt][1], af[mt][2], af[mt][3],
                        as_u + (row * ASH + col) * 2);
            }
#pragma unroll
            for (int np = 0; np < 4; np++) {
                const int k = ks * 16 + b_lk;
                const int n = warp_n * 64 + np * 16 + b_ln;
                ldsm_x4t(bf[2 * np][0], bf[2 * np][1], bf[2 * np + 1][0], bf[2 * np + 1][1],
                         bs_u + (k * BSH + n) * 2);
            }
#pragma unroll
            for (int mt = 0; mt < 2; mt++)
#pragma unroll
                for (int nt = 0; nt < 8; nt++)
                    mma_f16(acc[mt][nt], af[mt], bf[nt]);
        }
        __syncthreads();
    }

    // Epilogue
#pragma unroll
    for (int mt = 0; mt < 2; mt++) {
#pragma unroll
        for (int nt = 0; nt < 8; nt++) {
            const int r = brow + warp_m * 32 + mt * 16 + lg;
            const int c = bcol + warp_n * 64 + nt * 8 + 2 * lt;
#pragma unroll
            for (int h = 0; h < 2; h++) {
                const int rr = r + h * 8;
                float x0 = acc[mt][nt][h * 2 + 0];
                float x1 = acc[mt][nt][h * 2 + 1];
                if (EPI == 0) {
                    __half* C = (__half*)Cv;
                    *(__half2*)(C + (size_t)rr * N + c) = __floats2half2_rn(x0, x1);
                } else {
                    float* C = (float*)Cv;
                    const float* rp = resid + (size_t)rr * N + c;
                    float a0 = x0 + bias[c];
                    float a1 = x1 + bias[c + 1];
                    float g0 = 0.5f * a0 * (1.0f + erff(a0 * 0.70710678118654752f));
                    float g1 = 0.5f * a1 * (1.0f + erff(a1 * 0.70710678118654752f));
                    float2 o = {g0 + rp[0], g1 + rp[1]};
                    *(float2*)(C + (size_t)rr * N + c) = o;
                }
            }
        }
    }
}

// ---------------------------------------------------------------------------
// Kernel 4: attention over K=8 neighbors + spatial op, fp16 q/k/v.
// One block per point; warp h = head h; lane covers dims (2lane, 2lane+1).
// idx/displacement handled per-warp via shfl (no smem, no __syncthreads).
// ---------------------------------------------------------------------------
__global__ void __launch_bounds__(256) attn_kernel(const float* __restrict__ xyzs,
                                                   const float* __restrict__ w_sp) {
    const int p = blockIdx.x;
    const int b = p >> 11;
    const int warp = threadIdx.x >> 5;
    const int lane = threadIdx.x & 31;

    // lanes 0..7 load the 8 neighbor indices; broadcast via shfl
    int my_idx = 0;
    if (lane < KN) my_idx = __ldg(&g_idx[(size_t)p * KN + lane]);

    // lanes 0..7 compute displacement for their neighbor
    float dx = 0.f, dy = 0.f, dz = 0.f;
    if (lane < KN) {
        const float* xn = xyzs + ((size_t)b * NP + my_idx) * 3;
        const float* xq = xyzs + (size_t)p * 3;
        dx = xn[0] - xq[0];
        dy = xn[1] - xq[1];
        dz = xn[2] - xq[2];
    }

    const size_t qoff = (size_t)p * QKV3 + warp * DHD + 2 * lane;
    const __half2 q2 = *(const __half2*)(g_qkv_h + qoff);
    const float qx = __low2float(q2), qy = __high2float(q2);

    float logits[KN];
    int idxs[KN];
#pragma unroll
    for (int j = 0; j < KN; j++) idxs[j] = __shfl_sync(0xffffffffu, my_idx, j);

#pragma unroll
    for (int j = 0; j < KN; j++) {
        const size_t koff = ((size_t)b * NP + idxs[j]) * QKV3 + ID + warp * DHD + 2 * lane;
        const __half2 k2 = *(const __half2*)(g_qkv_h + koff);
        float d = qx * __low2float(k2) + qy * __high2float(k2);
#pragma unroll
        for (int o = 16; o; o >>= 1) d += __shfl_xor_sync(0xffffffffu, d, o);
        logits[j] = d * 0.125f;
    }

    float mx = logits[0];
#pragma unroll
    for (int j = 1; j < KN; j++) mx = fmaxf(mx, logits[j]);
    float a[KN];
    float se = 0.f;
#pragma unroll
    for (int j = 0; j < KN; j++) { a[j] = expf(logits[j] - mx); se += a[j]; }
    const float inv = 1.0f / se;
#pragma unroll
    for (int j = 0; j < KN; j++) a[j] *= inv;

    float oa = 0.f, ob = 0.f;
#pragma unroll
    for (int j = 0; j < KN; j++) {
        const size_t voff = ((size_t)b * NP + idxs[j]) * QKV3 + 2 * ID + warp * DHD + 2 * lane;
        const __half2 v2 = *(const __half2*)(g_qkv_h + voff);
        oa = fmaf(a[j], __low2float(v2), oa);
        ob = fmaf(a[j], __high2float(v2), ob);
    }

    // dis = max_j(a_j * disp_j); disp_j lives in lane j's (dx,dy,dz)
    float dm[3];
#pragma unroll
    for (int c = 0; c < 3; c++) {
        float m = -1e30f;
#pragma unroll
        for (int j = 0; j < KN; j++) {
            float dj = __shfl_sync(0xffffffffu, c == 0 ? dx : (c == 1 ? dy : dz), j);
            m = fmaxf(m, a[j] * dj);
        }
        dm[c] = m;
    }
    const int d0 = 2 * lane, d1 = 2 * lane + 1;
    const float da = dm[0] * w_sp[d0] + dm[1] * w_sp[64 + d0] + dm[2] * w_sp[128 + d0];
    const float db = dm[0] * w_sp[d1] + dm[1] * w_sp[64 + d1] + dm[2] * w_sp[128 + d1];

    __half2* op = (__half2*)(g_ao_h + (size_t)p * ID + warp * DHD + 2 * lane);
    *op = __floats2half2_rn(oa + da, ob + db);
}

// ---------------------------------------------------------------------------
extern "C" void kernel_launch(void* const* d_in, const int* in_sizes, int n_in,
                              void* d_out, int out_size) {
    (void)in_sizes; (void)n_in; (void)out_size;
    const float* xyzs    = (const float*)d_in[0];
    const float* feature = (const float*)d_in[1];
    const float* ln_g    = (const float*)d_in[2];
    const float* ln_b    = (const float*)d_in[3];
    const float* w_qkv   = (const float*)d_in[4];
    const float* w_sp    = (const float*)d_in[5];
    const float* w_out   = (const float*)d_in[6];
    const float* b_out   = (const float*)d_in[7];
    float* out = (float*)d_out;

    void *p_normed, *p_qkv, *p_ao, *p_wqkv, *p_wout;
    cudaGetSymbolAddress(&p_normed, g_normed_h);
    cudaGetSymbolAddress(&p_qkv, g_qkv_h);
    cudaGetSymbolAddress(&p_ao, g_ao_h);
    cudaGetSymbolAddress(&p_wqkv, g_wqkv_h);
    cudaGetSymbolAddress(&p_wout, g_wout_h);
    __half* normed = (__half*)p_normed;
    __half* qkv = (__half*)p_qkv;
    __half* ao = (__half*)p_ao;
    __half* wqkv = (__half*)p_wqkv;
    __half* wout = (__half*)p_wout;

    // weight conversions (independent of everything else)
    conv_kernel<<<(DF * QKV3) / 1024, 256>>>(w_qkv, wqkv);
    conv_kernel<<<(ID * DF) / 1024, 256>>>(w_out, wout);
    // 1) ball query
    ball_kernel<<<dim3(NP / 64, BQ), 256>>>(xyzs);
    // 2) layernorm -> fp16
    ln_kernel<<<(BQ * NP) / 8, 256>>>(feature, ln_g, ln_b);
    // 3) qkv = normed @ w_qkv   [32768 x 256] @ [256 x 1536] -> fp16
    hgemm_kernel<0><<<dim3(QKV3 / 128, (BQ * NP) / 128), 256>>>(
        normed, wqkv, qkv, QKV3, DF, nullptr, nullptr);
    // 4) attention + spatial op -> g_ao (fp16)
    attn_kernel<<<BQ * NP, 256>>>(xyzs, w_sp);
    // 5) out = gelu(ao @ w_out + b_out) + feature -> fp32
    hgemm_kernel<1><<<dim3(DF / 128, (BQ * NP) / 128), 256>>>(
        ao, wout, out, DF, ID, b_out, feature);
}

// round 7
// speedup vs baseline: 1.4646x; 1.0069x over previous
#include <cuda_runtime.h>
#include <cuda_fp16.h>
#include <math.h>
#include <stdint.h>

// Problem constants
#define BQ   16
#define NP   2048
#define DF   256
#define NH   8
#define DHD  64
#define KN   8
#define ID   512
#define QKV3 1536
#define RAD2 0.09f
#define LNEPS 1e-5f

// Scratch (static device globals; runtime allocation is forbidden)
__device__ int    g_idx[BQ * NP * KN];
__device__ __half g_normed_h[BQ * NP * DF];
__device__ __half g_qkv_h[BQ * NP * QKV3];
__device__ __half g_ao_h[BQ * NP * ID];
__device__ __half g_wqkv_h[DF * QKV3];
__device__ __half g_wout_h[ID * DF];

// ---------------------------------------------------------------------------
// PTX helpers
// ---------------------------------------------------------------------------
__device__ __forceinline__ void mma_f16(float* c, const uint32_t* a, const uint32_t* b) {
    asm volatile(
        "mma.sync.aligned.m16n8k16.row.col.f32.f16.f16.f32 "
        "{%0,%1,%2,%3}, {%4,%5,%6,%7}, {%8,%9}, {%0,%1,%2,%3};"
        : "+f"(c[0]), "+f"(c[1]), "+f"(c[2]), "+f"(c[3])
        : "r"(a[0]), "r"(a[1]), "r"(a[2]), "r"(a[3]), "r"(b[0]), "r"(b[1]));
}

__device__ __forceinline__ void ldsm_x4(uint32_t& r0, uint32_t& r1, uint32_t& r2,
                                        uint32_t& r3, uint32_t addr) {
    asm volatile("ldmatrix.sync.aligned.m8n8.x4.shared.b16 {%0,%1,%2,%3}, [%4];"
                 : "=r"(r0), "=r"(r1), "=r"(r2), "=r"(r3) : "r"(addr));
}
__device__ __forceinline__ void ldsm_x4t(uint32_t& r0, uint32_t& r1, uint32_t& r2,
                                         uint32_t& r3, uint32_t addr) {
    asm volatile("ldmatrix.sync.aligned.m8n8.x4.trans.shared.b16 {%0,%1,%2,%3}, [%4];"
                 : "=r"(r0), "=r"(r1), "=r"(r2), "=r"(r3) : "r"(addr));
}

__device__ __forceinline__ void cp16(uint32_t smem_dst, const void* gsrc) {
    asm volatile("cp.async.cg.shared.global [%0], [%1], 16;" :: "r"(smem_dst), "l"(gsrc));
}
__device__ __forceinline__ void cp_commit() { asm volatile("cp.async.commit_group;"); }
template <int N>
__device__ __forceinline__ void cp_wait() { asm volatile("cp.async.wait_group %0;" :: "n"(N)); }

// ---------------------------------------------------------------------------
// Kernel 1 "prep": LayerNorm (blocks 0..4095) + weight conversions
// (blocks 4096..4479 -> w_qkv, 4480..4607 -> w_out). One launch.
// ---------------------------------------------------------------------------
#define LN_BLOCKS 4096
#define CV1_BLOCKS 384   /* DF*QKV3/1024 */
#define CV2_BLOCKS 128   /* ID*DF/1024 */
#define PREP_BLOCKS (LN_BLOCKS + CV1_BLOCKS + CV2_BLOCKS)

__global__ void __launch_bounds__(256) prep_kernel(
    const float* __restrict__ feature, const float* __restrict__ gam,
    const float* __restrict__ bet, const float* __restrict__ w_qkv,
    const float* __restrict__ w_out) {
    const int bid = blockIdx.x;
    if (bid < LN_BLOCKS) {
        const int row = bid * 8 + (threadIdx.x >> 5);
        const int lane = threadIdx.x & 31;
        const float* f = feature + (size_t)row * DF + lane * 8;
        float v[8];
        float4 v0 = *(const float4*)f;
        float4 v1 = *(const float4*)(f + 4);
        v[0] = v0.x; v[1] = v0.y; v[2] = v0.z; v[3] = v0.w;
        v[4] = v1.x; v[5] = v1.y; v[6] = v1.z; v[7] = v1.w;
        float s = 0.f;
#pragma unroll
        for (int i = 0; i < 8; i++) s += v[i];
#pragma unroll
        for (int o = 16; o; o >>= 1) s += __shfl_xor_sync(0xffffffffu, s, o);
        const float mu = s * (1.0f / DF);
        float sq = 0.f;
#pragma unroll
        for (int i = 0; i < 8; i++) { float d = v[i] - mu; sq += d * d; }
#pragma unroll
        for (int o = 16; o; o >>= 1) sq += __shfl_xor_sync(0xffffffffu, sq, o);
        const float rs = rsqrtf(sq * (1.0f / DF) + LNEPS);
        const float* gp = gam + lane * 8;
        const float* bp = bet + lane * 8;
        __half2 o[4];
#pragma unroll
        for (int i = 0; i < 4; i++) {
            float a = (v[2 * i] - mu) * rs * gp[2 * i] + bp[2 * i];
            float c = (v[2 * i + 1] - mu) * rs * gp[2 * i + 1] + bp[2 * i + 1];
            o[i] = __floats2half2_rn(a, c);
        }
        __half2* op = (__half2*)(g_normed_h + (size_t)row * DF + lane * 8);
#pragma unroll
        for (int i = 0; i < 4; i++) op[i] = o[i];
    } else if (bid < LN_BLOCKS + CV1_BLOCKS) {
        const int i = ((bid - LN_BLOCKS) * 256 + threadIdx.x) * 4;
        float4 v = *(const float4*)(w_qkv + i);
        __half2* d = (__half2*)(g_wqkv_h + i);
        d[0] = __floats2half2_rn(v.x, v.y);
        d[1] = __floats2half2_rn(v.z, v.w);
    } else {
        const int i = ((bid - LN_BLOCKS - CV1_BLOCKS) * 256 + threadIdx.x) * 4;
        float4 v = *(const float4*)(w_out + i);
        __half2* d = (__half2*)(g_wout_h + i);
        d[0] = __floats2half2_rn(v.x, v.y);
        d[1] = __floats2half2_rn(v.z, v.w);
    }
}

// ---------------------------------------------------------------------------
// Kernel 2 "ballqkv": one launch containing
//   blocks [0, 128): ball_query, lane-per-query (256 queries per block)
//   blocks [128, 3200): qkv hgemm tiles (12 x 256 grid of 128x128 tiles)
// Union dynamic smem: ball uses 32KB float4 tile; qkv uses 37888B buffers.
// ---------------------------------------------------------------------------
#define BALL_BLOCKS 128
#define QKV_TILES_X 12
#define QKV_TILES_Y 256
#define ASH 40
#define BSH 136
#define AS_BYTES (128 * ASH * 2)              /* 10240 per buffer */
#define BS_BYTES (32 * BSH * 2)               /* 8704 per buffer */
#define FUSED_SMEM (2 * AS_BYTES + 2 * BS_BYTES)  /* 37888 >= 32768 ball */

__global__ void __launch_bounds__(256) ballqkv_kernel(
    const float* __restrict__ xyzs, const __half* __restrict__ A,
    const __half* __restrict__ Bm, __half* __restrict__ C) {
    extern __shared__ char smem_raw[];
    const int tid = threadIdx.x;

    if (blockIdx.x < BALL_BLOCKS) {
        // ---------------- ball query ----------------
        float4* sp = (float4*)smem_raw;           // 2048 * 16B = 32KB
        const int bb = blockIdx.x;
        const int b = bb >> 3;                     // batch
        const int n = ((bb & 7) << 8) + tid;       // query index in batch
        const float* xb = xyzs + (size_t)b * NP * 3;
        for (int m = tid; m < NP; m += 256) {
            float x = xb[3 * m], y = xb[3 * m + 1], z = xb[3 * m + 2];
            sp[m] = make_float4(x, y, z, x * x + y * y + z * z);
        }
        __syncthreads();
        const float4 q = sp[n];
        int i0 = 0, i1 = 0, i2 = 0, i3 = 0, i4 = 0, i5 = 0, i6 = 0, i7 = 0;
        int cnt = 0;
#pragma unroll 4
        for (int m = 0; m < NP; m++) {
            const float4 c = sp[m];
            const float d2 = q.w + c.w - 2.0f * (q.x * c.x + q.y * c.y + q.z * c.z);
            if (d2 < RAD2 && cnt < KN) {
                if      (cnt == 0) i0 = m;
                else if (cnt == 1) i1 = m;
                else if (cnt == 2) i2 = m;
                else if (cnt == 3) i3 = m;
                else if (cnt == 4) i4 = m;
                else if (cnt == 5) i5 = m;
                else if (cnt == 6) i6 = m;
                else               i7 = m;
                cnt++;
            }
        }
        // pad with first found (cnt >= 1 always: self within radius)
        int* op = g_idx + ((size_t)b * NP + n) * KN;
        op[0] = i0;
        op[1] = (cnt > 1) ? i1 : i0;
        op[2] = (cnt > 2) ? i2 : i0;
        op[3] = (cnt > 3) ? i3 : i0;
        op[4] = (cnt > 4) ? i4 : i0;
        op[5] = (cnt > 5) ? i5 : i0;
        op[6] = (cnt > 6) ? i6 : i0;
        op[7] = (cnt > 7) ? i7 : i0;
        return;
    }

    // ---------------- qkv hgemm tile ----------------
    __half* As[2] = {(__half*)smem_raw, (__half*)(smem_raw + AS_BYTES)};
    __half* Bs[2] = {(__half*)(smem_raw + 2 * AS_BYTES),
                     (__half*)(smem_raw + 2 * AS_BYTES + BS_BYTES)};

    const int t = blockIdx.x - BALL_BLOCKS;
    const int bcol = (t % QKV_TILES_X) * 128;
    const int brow = (t / QKV_TILES_X) * 128;
    const int N = QKV3, Kd = DF;
    const int KT = Kd / 32;   // 8

    const int warp = tid >> 5, lane = tid & 31;
    const int warp_m = warp >> 1, warp_n = warp & 1;

    const int a_r0 = tid >> 2;
    const int a_c = (tid & 3) * 8;
    const int b_r0 = tid >> 4;
    const int b_c = (tid & 15) * 8;

    auto load_tile = [&](int kt, int buf) {
        const uint32_t as_base = (uint32_t)__cvta_generic_to_shared(As[buf]);
        const uint32_t bs_base = (uint32_t)__cvta_generic_to_shared(Bs[buf]);
#pragma unroll
        for (int i = 0; i < 2; i++) {
            const int row = a_r0 + 64 * i;
            cp16(as_base + (row * ASH + a_c) * 2,
                 A + (size_t)(brow + row) * Kd + kt * 32 + a_c);
        }
#pragma unroll
        for (int i = 0; i < 2; i++) {
            const int row = b_r0 + 16 * i;
            cp16(bs_base + (row * BSH + b_c) * 2,
                 Bm + (size_t)(kt * 32 + row) * N + bcol + b_c);
        }
        cp_commit();
    };

    float acc[2][8][4];
#pragma unroll
    for (int mt = 0; mt < 2; mt++)
#pragma unroll
        for (int nt = 0; nt < 8; nt++)
#pragma unroll
            for (int r = 0; r < 4; r++) acc[mt][nt][r] = 0.f;

    load_tile(0, 0);

    const int lg = lane >> 2;
    const int lt = lane & 3;
    const int a_lrow = (lane & 15);
    const int a_lcol = ((lane >> 4) << 3);
    const int b_lk = (lane & 7) + ((lane >> 3) & 1) * 8;
    const int b_ln = ((lane >> 4) << 3);

    for (int kt = 0; kt < KT; kt++) {
        const int buf = kt & 1;
        if (kt + 1 < KT) {
            load_tile(kt + 1, buf ^ 1);
            cp_wait<1>();
        } else {
            cp_wait<0>();
        }
        __syncthreads();

        const uint32_t as_u = (uint32_t)__cvta_generic_to_shared(As[buf]);
        const uint32_t bs_u = (uint32_t)__cvta_generic_to_shared(Bs[buf]);
#pragma unroll
        for (int ks = 0; ks < 2; ks++) {
            uint32_t af[2][4], bf[8][2];
#pragma unroll
            for (int mt = 0; mt < 2; mt++) {
                const int row = warp_m * 32 + mt * 16 + a_lrow;
                const int col = ks * 16 + a_lcol;
                ldsm_x4(af[mt][0], af[mt][1], af[mt][2], af[mt][3],
                        as_u + (row * ASH + col) * 2);
            }
#pragma unroll
            for (int np = 0; np < 4; np++) {
                const int k = ks * 16 + b_lk;
                const int n = warp_n * 64 + np * 16 + b_ln;
                ldsm_x4t(bf[2 * np][0], bf[2 * np][1], bf[2 * np + 1][0], bf[2 * np + 1][1],
                         bs_u + (k * BSH + n) * 2);
            }
#pragma unroll
            for (int mt = 0; mt < 2; mt++)
#pragma unroll
                for (int nt = 0; nt < 8; nt++)
                    mma_f16(acc[mt][nt], af[mt], bf[nt]);
        }
        __syncthreads();
    }

#pragma unroll
    for (int mt = 0; mt < 2; mt++)
#pragma unroll
        for (int nt = 0; nt < 8; nt++) {
            const int r = brow + warp_m * 32 + mt * 16 + lg;
            const int c = bcol + warp_n * 64 + nt * 8 + 2 * lt;
#pragma unroll
            for (int h = 0; h < 2; h++) {
                const int rr = r + h * 8;
                *(__half2*)(C + (size_t)rr * N + c) =
                    __floats2half2_rn(acc[mt][nt][h * 2 + 0], acc[mt][nt][h * 2 + 1]);
            }
        }
}

// ---------------------------------------------------------------------------
// Kernel 3: attention over K=8 neighbors + spatial op, fp16 q/k/v.
// ---------------------------------------------------------------------------
__global__ void __launch_bounds__(256) attn_kernel(const float* __restrict__ xyzs,
                                                   const float* __restrict__ w_sp) {
    const int p = blockIdx.x;
    const int b = p >> 11;
    const int warp = threadIdx.x >> 5;
    const int lane = threadIdx.x & 31;

    int my_idx = 0;
    if (lane < KN) my_idx = __ldg(&g_idx[(size_t)p * KN + lane]);

    float dx = 0.f, dy = 0.f, dz = 0.f;
    if (lane < KN) {
        const float* xn = xyzs + ((size_t)b * NP + my_idx) * 3;
        const float* xq = xyzs + (size_t)p * 3;
        dx = xn[0] - xq[0];
        dy = xn[1] - xq[1];
        dz = xn[2] - xq[2];
    }

    const size_t qoff = (size_t)p * QKV3 + warp * DHD + 2 * lane;
    const __half2 q2 = *(const __half2*)(g_qkv_h + qoff);
    const float qx = __low2float(q2), qy = __high2float(q2);

    float logits[KN];
    int idxs[KN];
#pragma unroll
    for (int j = 0; j < KN; j++) idxs[j] = __shfl_sync(0xffffffffu, my_idx, j);

#pragma unroll
    for (int j = 0; j < KN; j++) {
        const size_t koff = ((size_t)b * NP + idxs[j]) * QKV3 + ID + warp * DHD + 2 * lane;
        const __half2 k2 = *(const __half2*)(g_qkv_h + koff);
        float d = qx * __low2float(k2) + qy * __high2float(k2);
#pragma unroll
        for (int o = 16; o; o >>= 1) d += __shfl_xor_sync(0xffffffffu, d, o);
        logits[j] = d * 0.125f;
    }

    float mx = logits[0];
#pragma unroll
    for (int j = 1; j < KN; j++) mx = fmaxf(mx, logits[j]);
    float a[KN];
    float se = 0.f;
#pragma unroll
    for (int j = 0; j < KN; j++) { a[j] = expf(logits[j] - mx); se += a[j]; }
    const float inv = 1.0f / se;
#pragma unroll
    for (int j = 0; j < KN; j++) a[j] *= inv;

    float oa = 0.f, ob = 0.f;
#pragma unroll
    for (int j = 0; j < KN; j++) {
        const size_t voff = ((size_t)b * NP + idxs[j]) * QKV3 + 2 * ID + warp * DHD + 2 * lane;
        const __half2 v2 = *(const __half2*)(g_qkv_h + voff);
        oa = fmaf(a[j], __low2float(v2), oa);
        ob = fmaf(a[j], __high2float(v2), ob);
    }

    float dm[3];
#pragma unroll
    for (int c = 0; c < 3; c++) {
        float m = -1e30f;
#pragma unroll
        for (int j = 0; j < KN; j++) {
            float dj = __shfl_sync(0xffffffffu, c == 0 ? dx : (c == 1 ? dy : dz), j);
            m = fmaxf(m, a[j] * dj);
        }
        dm[c] = m;
    }
    const int d0 = 2 * lane, d1 = 2 * lane + 1;
    const float da = dm[0] * w_sp[d0] + dm[1] * w_sp[64 + d0] + dm[2] * w_sp[128 + d0];
    const float db = dm[0] * w_sp[d1] + dm[1] * w_sp[64 + d1] + dm[2] * w_sp[128 + d1];

    __half2* op = (__half2*)(g_ao_h + (size_t)p * ID + warp * DHD + 2 * lane);
    *op = __floats2half2_rn(oa + da, ob + db);
}

// ---------------------------------------------------------------------------
// Kernel 4: out GEMM (fp16 A/B, fp32 accum) + bias + exact GELU + residual.
// ---------------------------------------------------------------------------
__global__ void __launch_bounds__(256) out_gemm_kernel(
    const __half* __restrict__ A, const __half* __restrict__ Bm, float* __restrict__ C,
    const float* __restrict__ bias, const float* __restrict__ resid) {
    __shared__ __half As[2][128 * ASH];
    __shared__ __half Bs[2][32 * BSH];
    const int N = DF, Kd = ID;

    const int tid = threadIdx.x;
    const int warp = tid >> 5, lane = tid & 31;
    const int warp_m = warp >> 1, warp_n = warp & 1;
    const int brow = blockIdx.y * 128;
    const int bcol = blockIdx.x * 128;
    const int KT = Kd / 32;

    const int a_r0 = tid >> 2;
    const int a_c = (tid & 3) * 8;
    const int b_r0 = tid >> 4;
    const int b_c = (tid & 15) * 8;

    auto load_tile = [&](int kt, int buf) {
        const uint32_t as_base = (uint32_t)__cvta_generic_to_shared(&As[buf][0]);
        const uint32_t bs_base = (uint32_t)__cvta_generic_to_shared(&Bs[buf][0]);
#pragma unroll
        for (int i = 0; i < 2; i++) {
            const int row = a_r0 + 64 * i;
            cp16(as_base + (row * ASH + a_c) * 2,
                 A + (size_t)(brow + row) * Kd + kt * 32 + a_c);
        }
#pragma unroll
        for (int i = 0; i < 2; i++) {
            const int row = b_r0 + 16 * i;
            cp16(bs_base + (row * BSH + b_c) * 2,
                 Bm + (size_t)(kt * 32 + row) * N + bcol + b_c);
        }
        cp_commit();
    };

    float acc[2][8][4];
#pragma unroll
    for (int mt = 0; mt < 2; mt++)
#pragma unroll
        for (int nt = 0; nt < 8; nt++)
#pragma unroll
            for (int r = 0; r < 4; r++) acc[mt][nt][r] = 0.f;

    load_tile(0, 0);

    const int lg = lane >> 2;
    const int lt = lane & 3;
    const int a_lrow = (lane & 15);
    const int a_lcol = ((lane >> 4) << 3);
    const int b_lk = (lane & 7) + ((lane >> 3) & 1) * 8;
    const int b_ln = ((lane >> 4) << 3);

    for (int kt = 0; kt < KT; kt++) {
        const int buf = kt & 1;
        if (kt + 1 < KT) {
            load_tile(kt + 1, buf ^ 1);
            cp_wait<1>();
        } else {
            cp_wait<0>();
        }
        __syncthreads();

        const uint32_t as_u = (uint32_t)__cvta_generic_to_shared(&As[buf][0]);
        const uint32_t bs_u = (uint32_t)__cvta_generic_to_shared(&Bs[buf][0]);
#pragma unroll
        for (int ks = 0; ks < 2; ks++) {
            uint32_t af[2][4], bf[8][2];
#pragma unroll
            for (int mt = 0; mt < 2; mt++) {
                const int row = warp_m * 32 + mt * 16 + a_lrow;
                const int col = ks * 16 + a_lcol;
                ldsm_x4(af[mt][0], af[mt][1], af[mt][2], af[mt][3],
                        as_u + (row * ASH + col) * 2);
            }
#pragma unroll
            for (int np = 0; np < 4; np++) {
                const int k = ks * 16 + b_lk;
                const int n = warp_n * 64 + np * 16 + b_ln;
                ldsm_x4t(bf[2 * np][0], bf[2 * np][1], bf[2 * np + 1][0], bf[2 * np + 1][1],
                         bs_u + (k * BSH + n) * 2);
            }
#pragma unroll
            for (int mt = 0; mt < 2; mt++)
#pragma unroll
                for (int nt = 0; nt < 8; nt++)
                    mma_f16(acc[mt][nt], af[mt], bf[nt]);
        }
        __syncthreads();
    }

#pragma unroll
    for (int mt = 0; mt < 2; mt++)
#pragma unroll
        for (int nt = 0; nt < 8; nt++) {
            const int r = brow + warp_m * 32 + mt * 16 + lg;
            const int c = bcol + warp_n * 64 + nt * 8 + 2 * lt;
#pragma unroll
            for (int h = 0; h < 2; h++) {
                const int rr = r + h * 8;
                const float* rp = resid + (size_t)rr * N + c;
                float a0 = acc[mt][nt][h * 2 + 0] + bias[c];
                float a1 = acc[mt][nt][h * 2 + 1] + bias[c + 1];
                float g0 = 0.5f * a0 * (1.0f + erff(a0 * 0.70710678118654752f));
                float g1 = 0.5f * a1 * (1.0f + erff(a1 * 0.70710678118654752f));
                float2 o = {g0 + rp[0], g1 + rp[1]};
                *(float2*)(C + (size_t)rr * N + c) = o;
            }
        }
}

// ---------------------------------------------------------------------------
extern "C" void kernel_launch(void* const* d_in, const int* in_sizes, int n_in,
                              void* d_out, int out_size) {
    (void)in_sizes; (void)n_in; (void)out_size;
    const float* xyzs    = (const float*)d_in[0];
    const float* feature = (const float*)d_in[1];
    const float* ln_g    = (const float*)d_in[2];
    const float* ln_b    = (const float*)d_in[3];
    const float* w_qkv   = (const float*)d_in[4];
    const float* w_sp    = (const float*)d_in[5];
    const float* w_out   = (const float*)d_in[6];
    const float* b_out   = (const float*)d_in[7];
    float* out = (float*)d_out;

    void *p_normed, *p_qkv, *p_ao, *p_wqkv, *p_wout;
    cudaGetSymbolAddress(&p_normed, g_normed_h);
    cudaGetSymbolAddress(&p_qkv, g_qkv_h);
    cudaGetSymbolAddress(&p_ao, g_ao_h);
    cudaGetSymbolAddress(&p_wqkv, g_wqkv_h);
    cudaGetSymbolAddress(&p_wout, g_wout_h);
    __half* normed = (__half*)p_normed;
    __half* qkv = (__half*)p_qkv;
    __half* ao = (__half*)p_ao;
    __half* wqkv = (__half*)p_wqkv;
    __half* wout = (__half*)p_wout;

    // 1) prep: layernorm -> fp16, plus both weight conversions
    prep_kernel<<<PREP_BLOCKS, 256>>>(feature, ln_g, ln_b, w_qkv, w_out);
    // 2) fused ball query + qkv GEMM (independent work, one launch)
    ballqkv_kernel<<<BALL_BLOCKS + QKV_TILES_X * QKV_TILES_Y, 256, FUSED_SMEM>>>(
        xyzs, normed, wqkv, qkv);
    // 3) attention + spatial op -> g_ao (fp16)
    attn_kernel<<<BQ * NP, 256>>>(xyzs, w_sp);
    // 4) out = gelu(ao @ w_out + b_out) + feature -> fp32
    out_gemm_kernel<<<dim3(DF / 128, (BQ * NP) / 128), 256>>>(
        ao, wout, out, b_out, feature);
}